// round 6
// baseline (speedup 1.0000x reference)
#include <cuda_runtime.h>

#define RR 4
#define ND 81
#define HH 128
#define WW 256
#define CC 128
#define BB 8
#define HW (HH*WW)

#define HT 8                 // tile height
#define WT 16                // tile width
#define PW 4                 // pixels per thread (w)
#define CB 4                 // channels per stage
#define NCHUNK (CC/CB)       // 32
#define NSTG 4               // pipeline ring
#define WROWS (HT + 2*RR)    // 16 warped rows per channel
#define WROW 28              // warped row stride (floats); 24 used
#define XROW 20              // x row stride (floats); 16 used
#define WCH (WROWS*WROW)     // 448
#define XCH (HT*XROW)        // 160
#define CHSZ (WCH + XCH)     // 608 floats / channel
#define STG (CB*CHSZ)        // 2432 floats / stage
#define SMEM_BYTES (NSTG * STG * 4)   // 38912
#define NTHR 288             // 72 (h_i,di) combos * 4 wgroups

typedef unsigned long long u64t;

// thread remap: r = tid%72 -> (h_i, dig) enumerated s-major (s = h_i + dig),
// so lanes sharing a warped window row are adjacent -> LDS broadcast dedup.
__constant__ unsigned char TH[72] = {
    0,                      // s=0
    0,1,                    // s=1
    0,1,2,                  // s=2
    0,1,2,3,                // s=3
    0,1,2,3,4,              // s=4
    0,1,2,3,4,5,            // s=5
    0,1,2,3,4,5,6,          // s=6
    0,1,2,3,4,5,6,7,        // s=7
    0,1,2,3,4,5,6,7,        // s=8
    1,2,3,4,5,6,7,          // s=9
    2,3,4,5,6,7,            // s=10
    3,4,5,6,7,              // s=11
    4,5,6,7,                // s=12
    5,6,7,                  // s=13
    6,7,                    // s=14
    7                       // s=15
};
__constant__ unsigned char TS[72] = {
    0,
    1,1,
    2,2,2,
    3,3,3,3,
    4,4,4,4,4,
    5,5,5,5,5,5,
    6,6,6,6,6,6,6,
    7,7,7,7,7,7,7,7,
    8,8,8,8,8,8,8,8,
    9,9,9,9,9,9,9,
    10,10,10,10,10,10,
    11,11,11,11,11,
    12,12,12,12,
    13,13,13,
    14,14,
    15
};

static __device__ __forceinline__ u64t pk2(float lo, float hi) {
    return __double_as_longlong(__hiloint2double(__float_as_int(hi), __float_as_int(lo)));
}
static __device__ __forceinline__ void fma2(u64t &acc, u64t a, u64t b) {
    asm("fma.rn.f32x2 %0, %1, %2, %0;" : "+l"(acc) : "l"(a), "l"(b));
}
static __device__ __forceinline__ float lo32(u64t v) {
    return __int_as_float(__double2loint(__longlong_as_double(v)));
}
static __device__ __forceinline__ float hi32(u64t v) {
    return __int_as_float(__double2hiint(__longlong_as_double(v)));
}
static __device__ __forceinline__ void cpa16(unsigned dst, const float* src) {
    asm volatile("cp.async.cg.shared.global [%0], [%1], 16;" :: "r"(dst), "l"(src));
}

extern __shared__ __align__(16) float smf[];

__global__ void __launch_bounds__(NTHR, 3)
cost_volume_kernel(const float* __restrict__ gx, const float* __restrict__ gw,
                   float* __restrict__ gout)
{
    const int tid = threadIdx.x;
    const int w0  = blockIdx.x * WT;
    const int h0  = blockIdx.y * HT;
    const int b   = blockIdx.z;

    const float* xb = gx + (size_t)b * CC * HW;
    const float* wb = gw + (size_t)b * CC * HW;
    const unsigned smb = (unsigned)__cvta_generic_to_shared(smf);

    // ---------- staging role: ONE float4 per thread per channel, fully hoisted ----------
    const float* gsrc = nullptr;
    int smoff = 0;
    bool active = false;

    if (tid < 96) {                           // warped halo: 16 rows x 6 quads
        const int row = tid / 6, q = tid % 6;
        const int gh   = h0 - RR + row;
        const int gcol = w0 - RR + q * 4;
        smoff = row * WROW + q * 4;
        const bool valid = ((unsigned)gh < HH) && (gcol >= 0) && (gcol + 4 <= WW);
        if (valid) { gsrc = wb + (size_t)gh * WW + gcol; active = true; }
        else {
            #pragma unroll
            for (int s = 0; s < NSTG; s++)
                #pragma unroll
                for (int cc2 = 0; cc2 < CB; cc2++)
                    *(float4*)(smf + s * STG + cc2 * CHSZ + smoff) =
                        make_float4(0.f, 0.f, 0.f, 0.f);
        }
    } else if (tid < 128) {                   // x tile: 8 rows x 4 quads
        const int i = tid - 96;
        const int row = i / 4, q = i % 4;
        smoff = WCH + row * XROW + q * 4;
        gsrc  = xb + (size_t)(h0 + row) * WW + w0 + q * 4;
        active = true;
    }

    unsigned sdst[NSTG];
    #pragma unroll
    for (int s = 0; s < NSTG; s++) sdst[s] = smb + (unsigned)((s * STG + smoff) * 4);

    const float* srcp = gsrc;
    auto do_stage = [&](int chunk, int s) {
        if (chunk < NCHUNK) {
            if (active) {
                #pragma unroll
                for (int cc2 = 0; cc2 < CB; cc2++)
                    cpa16(sdst[s] + (unsigned)(cc2 * CHSZ * 4), srcp + cc2 * HW);
                srcp += CB * HW;
            }
        }
        asm volatile("cp.async.commit_group;" ::: "memory");
    };

    // ---------- compute role: s-major remap ----------
    const int wg  = tid / 72;          // 0..3 (warps mostly single-wg)
    const int r   = tid - wg * 72;     // 0..71
    const int h_i = (int)TH[r];
    const int srow = (int)TS[r];       // = h_i + dig
    const int dig = srow - h_i;        // di + 4

    const int woff = srow * WROW + wg * PW;        // 16B aligned; shared across group
    const int xoff = WCH + h_i * XROW + wg * PW;   // 16B aligned

    u64t acc[18];                      // [dj(9)][pixel-pair(2)]
    #pragma unroll
    for (int i = 0; i < 18; i++) acc[i] = 0ULL;

    do_stage(0, 0);
    do_stage(1, 1);
    do_stage(2, 2);

    auto body = [&](int chunk, int stage) {
        asm volatile("cp.async.wait_group 2;" ::: "memory");
        __syncthreads();

        const float* sb = smf + stage * STG;
        #pragma unroll
        for (int cc2 = 0; cc2 < CB; cc2++) {
            const float* base = sb + cc2 * CHSZ;
            const float4* wv4 = (const float4*)(base + woff);
            const float4* xv4 = (const float4*)(base + xoff);

            float wr[12];
            #pragma unroll
            for (int k = 0; k < 3; k++) {
                float4 t = wv4[k];
                wr[4*k+0] = t.x; wr[4*k+1] = t.y; wr[4*k+2] = t.z; wr[4*k+3] = t.w;
            }
            float4 x0 = xv4[0];
            u64t xv[2];
            xv[0] = pk2(x0.x, x0.y);
            xv[1] = pk2(x0.z, x0.w);

            #pragma unroll
            for (int p = 0; p < 2; p++) {
                #pragma unroll
                for (int dj = 0; dj < 9; dj++) {
                    fma2(acc[dj * 2 + p], xv[p], pk2(wr[2*p + dj], wr[2*p + dj + 1]));
                }
            }
        }

        do_stage(chunk + 3, (chunk + 3) & (NSTG - 1));
    };

    #pragma unroll 1
    for (int c = 0; c < NCHUNK; c += 4) {
        body(c + 0, 0);
        body(c + 1, 1);
        body(c + 2, 2);
        body(c + 3, 3);
    }

    // ---------- epilogue ----------
    const float sc = 1.0f / (float)(CC * ND);
    float* ob = gout + (((size_t)b * ND + dig * 9) * HH + (h0 + h_i)) * WW + w0 + wg * PW;
    #pragma unroll
    for (int dj = 0; dj < 9; dj++) {
        float* od = ob + (size_t)dj * HW;
        #pragma unroll
        for (int p = 0; p < 2; p++) {
            u64t v = acc[dj * 2 + p];
            float2 r2;
            r2.x = lo32(v) * sc;
            r2.y = hi32(v) * sc;
            *(float2*)(od + 2 * p) = r2;
        }
    }
}

extern "C" void kernel_launch(void* const* d_in, const int* in_sizes, int n_in,
                              void* d_out, int out_size) {
    const float* x = (const float*)d_in[0];
    const float* w = (const float*)d_in[1];
    float* out = (float*)d_out;
    cudaFuncSetAttribute(cost_volume_kernel,
                         cudaFuncAttributeMaxDynamicSharedMemorySize, SMEM_BYTES);
    dim3 grid(WW / WT, HH / HT, BB);   // (16, 16, 8) = 2048 blocks
    cost_volume_kernel<<<grid, NTHR, SMEM_BYTES>>>(x, w, out);
}